// round 9
// baseline (speedup 1.0000x reference)
#include <cuda_runtime.h>
#include <math.h>

#define N_NODES 100000
#define N_EDGES 3200000
#define IN_CH   256
#define HID     16
#define OUT_CH  40
#define CAP     96      // max in-degree capacity (Poisson(32): P(>=96) ~ 1e-18)
#define GEMM_CHUNKS ((N_NODES + 255) / 256)   // 391

// ---- scratch (static device globals; referenced ONLY inside kernels) ----
__device__ int      g_is64;
__device__ int      g_cnt   [N_NODES];
__device__ int      g_bucket[(size_t)N_NODES * CAP];
__device__ float    g_dinv  [N_NODES];
__device__ float4   g_t1s   [N_NODES * 4];  // x@W1 raw, then scaled in phase 2
__device__ float4   g_hs    [N_NODES * 4];  // relu(layer1) * dinv
__device__ unsigned g_bar[2];               // [0]=arrive count, [1]=release epoch

// ---------------------------------------------------------------
// grid barrier (sense = monotonically increasing epoch). All blocks are
// resident (grid sized via occupancy API), so spinning is safe.
__device__ __forceinline__ void gridbar(unsigned& ph) {
    __syncthreads();
    if (threadIdx.x == 0) {
        __threadfence();
        unsigned nb = gridDim.x;
        if (atomicAdd(&g_bar[0], 1u) == nb - 1u) {
            g_bar[0] = 0u;
            __threadfence();
            atomicExch(&g_bar[1], ph + 1u);
        } else {
            while (*(volatile unsigned*)&g_bar[1] <= ph) __nanosleep(64);
        }
        __threadfence();
    }
    __syncthreads();
    ph++;
}

// ---------------------------------------------------------------
__global__ void __launch_bounds__(256) k_fused(
    const float* __restrict__ x, const void* __restrict__ ei,
    const float* __restrict__ W1, const float* __restrict__ b1,
    const float* __restrict__ W2, const float* __restrict__ b2,
    float* __restrict__ out)
{
    __shared__ float xs[32][257];
    int t   = threadIdx.x;
    int bid = blockIdx.x;
    int gtid = bid * 256 + t;
    int gsz  = gridDim.x * 256;
    unsigned ph = 0;

    // ---- Phase 0: zero counts, detect index dtype ----
    for (int i = gtid; i < N_NODES; i += gsz) g_cnt[i] = 0;
    if (bid == 0 && t < 32) {
        const int* e32 = (const int*)ei;
        int bad = 0;
        for (int j = t; j < 128; j += 32) bad |= (__ldg(&e32[2 * j + 1]) != 0);
        unsigned m = __ballot_sync(0xffffffffu, bad);
        if (t == 0) g_is64 = (m == 0u);
    }
    gridbar(ph);

    // ---- Phase 1: build (blocks [0,BB)) CONCURRENT with gemm1 (rest) ----
    {
        int BB = gridDim.x / 4;
        if (bid < BB) {
            const int nI4 = N_EDGES / 4;
            int is64 = g_is64;
            for (int i4 = bid * 256 + t; i4 < nI4; i4 += BB * 256) {
                int r[4], c[4];
                if (!is64) {
                    const int* e = (const int*)ei;
                    int4 rv = __ldg((const int4*)e + i4);
                    int4 cv = __ldg((const int4*)(e + N_EDGES) + i4);
                    r[0] = rv.x; r[1] = rv.y; r[2] = rv.z; r[3] = rv.w;
                    c[0] = cv.x; c[1] = cv.y; c[2] = cv.z; c[3] = cv.w;
                } else {
                    const long long* e = (const long long*)ei;
                    longlong2 a0 = __ldg((const longlong2*)e + i4 * 2);
                    longlong2 a1 = __ldg((const longlong2*)e + i4 * 2 + 1);
                    longlong2 b0 = __ldg((const longlong2*)(e + N_EDGES) + i4 * 2);
                    longlong2 b1v = __ldg((const longlong2*)(e + N_EDGES) + i4 * 2 + 1);
                    r[0] = (int)a0.x; r[1] = (int)a0.y; r[2] = (int)a1.x; r[3] = (int)a1.y;
                    c[0] = (int)b0.x; c[1] = (int)b0.y; c[2] = (int)b1v.x; c[3] = (int)b1v.y;
                }
#pragma unroll
                for (int k = 0; k < 4; k++) {
                    int pos = atomicAdd(&g_cnt[c[k]], 1);
                    if (pos < CAP) g_bucket[(size_t)c[k] * CAP + pos] = r[k];
                }
            }
        } else {
            // register-tiled gemm1: 1 thread = 1 node, 16 accumulators.
            // W1 read via uniform LDG broadcast (L1-cached); x transposed via smem.
            int f4 = t & 7, nl = t >> 3;
            for (int ch = bid - BB; ch < GEMM_CHUNKS; ch += gridDim.x - BB) {
                int node0 = ch * 256;
                float acc[16];
#pragma unroll
                for (int h = 0; h < 16; h++) acc[h] = 0.f;
#pragma unroll 1
                for (int kc = 0; kc < 256; kc += 32) {
                    __syncthreads();
#pragma unroll
                    for (int rep = 0; rep < 8; rep++) {
                        int n = nl + 32 * rep;
                        int node = node0 + n;
                        float4 v = (node < N_NODES)
                            ? __ldg((const float4*)(x + (size_t)node * 256 + kc) + f4)
                            : make_float4(0.f, 0.f, 0.f, 0.f);
                        xs[f4 * 4 + 0][n] = v.x;
                        xs[f4 * 4 + 1][n] = v.y;
                        xs[f4 * 4 + 2][n] = v.z;
                        xs[f4 * 4 + 3][n] = v.w;
                    }
                    __syncthreads();
#pragma unroll 8
                    for (int k = 0; k < 32; k++) {
                        float xr = xs[k][t];
                        const float4* w = (const float4*)(W1 + (size_t)(kc + k) * 16);
                        float4 w0 = __ldg(w), w1 = __ldg(w + 1);
                        float4 w2 = __ldg(w + 2), w3 = __ldg(w + 3);
                        acc[0]  = fmaf(xr, w0.x, acc[0]);
                        acc[1]  = fmaf(xr, w0.y, acc[1]);
                        acc[2]  = fmaf(xr, w0.z, acc[2]);
                        acc[3]  = fmaf(xr, w0.w, acc[3]);
                        acc[4]  = fmaf(xr, w1.x, acc[4]);
                        acc[5]  = fmaf(xr, w1.y, acc[5]);
                        acc[6]  = fmaf(xr, w1.z, acc[6]);
                        acc[7]  = fmaf(xr, w1.w, acc[7]);
                        acc[8]  = fmaf(xr, w2.x, acc[8]);
                        acc[9]  = fmaf(xr, w2.y, acc[9]);
                        acc[10] = fmaf(xr, w2.z, acc[10]);
                        acc[11] = fmaf(xr, w2.w, acc[11]);
                        acc[12] = fmaf(xr, w3.x, acc[12]);
                        acc[13] = fmaf(xr, w3.y, acc[13]);
                        acc[14] = fmaf(xr, w3.z, acc[14]);
                        acc[15] = fmaf(xr, w3.w, acc[15]);
                    }
                }
                int node = node0 + t;
                if (node < N_NODES) {
#pragma unroll
                    for (int q = 0; q < 4; q++)
                        g_t1s[node * 4 + q] = make_float4(acc[q * 4 + 0], acc[q * 4 + 1],
                                                          acc[q * 4 + 2], acc[q * 4 + 3]);
                }
            }
        }
    }
    gridbar(ph);

    // ---- Phase 2: dinv + scale t1 in place ----
    for (int i = gtid; i < N_NODES * 4; i += gsz) {
        int node = i >> 2, q = i & 3;
        float d = rsqrtf(1.0f + (float)g_cnt[node]);
        if (q == 0) g_dinv[node] = d;
        float4 v = g_t1s[i];
        v.x *= d; v.y *= d; v.z *= d; v.w *= d;
        g_t1s[i] = v;
    }
    gridbar(ph);

    // ---- Phase 3: layer-1 pull aggregate -> g_hs ----
    for (int i = gtid; i < N_NODES * 4; i += gsz) {
        int node = i >> 2, q = i & 3;
        int cnt = g_cnt[node]; if (cnt > CAP) cnt = CAP;
        const int* bk = g_bucket + (size_t)node * CAP;
        const float4* __restrict__ src = g_t1s;
        float4 acc = src[node * 4 + q];
        int j = 0;
        for (; j + 8 <= cnt; j += 8) {
            int4 i0 = *(const int4*)(bk + j);
            int4 i1 = *(const int4*)(bk + j + 4);
            float4 v0 = src[i0.x * 4 + q], v1 = src[i0.y * 4 + q];
            float4 v2 = src[i0.z * 4 + q], v3 = src[i0.w * 4 + q];
            float4 v4 = src[i1.x * 4 + q], v5 = src[i1.y * 4 + q];
            float4 v6 = src[i1.z * 4 + q], v7 = src[i1.w * 4 + q];
            acc.x += ((v0.x + v1.x) + (v2.x + v3.x)) + ((v4.x + v5.x) + (v6.x + v7.x));
            acc.y += ((v0.y + v1.y) + (v2.y + v3.y)) + ((v4.y + v5.y) + (v6.y + v7.y));
            acc.z += ((v0.z + v1.z) + (v2.z + v3.z)) + ((v4.z + v5.z) + (v6.z + v7.z));
            acc.w += ((v0.w + v1.w) + (v2.w + v3.w)) + ((v4.w + v5.w) + (v6.w + v7.w));
        }
        for (; j < cnt; j++) {
            int r = __ldg(bk + j);
            float4 v = src[r * 4 + q];
            acc.x += v.x; acc.y += v.y; acc.z += v.z; acc.w += v.w;
        }
        float d = g_dinv[node];
        float4 h;
        h.x = fmaxf(fmaf(acc.x, d, __ldg(&b1[q * 4 + 0])), 0.f) * d;
        h.y = fmaxf(fmaf(acc.y, d, __ldg(&b1[q * 4 + 1])), 0.f) * d;
        h.z = fmaxf(fmaf(acc.z, d, __ldg(&b1[q * 4 + 2])), 0.f) * d;
        h.w = fmaxf(fmaf(acc.w, d, __ldg(&b1[q * 4 + 3])), 0.f) * d;
        g_hs[node * 4 + q] = h;
    }
    gridbar(ph);

    // ---- Phase 4: layer-2 aggregate + W2 GEMM + log_softmax, warp/node ----
    {
        int lane = t & 31;
        int gwarp = (bid * 256 + t) >> 5;
        int nwarps = gridDim.x * 8;
        int ch = lane & 15;
        int parity = lane >> 4;
        const float* __restrict__ hs = (const float*)g_hs;
        for (int node = gwarp; node < N_NODES; node += nwarps) {
            int cnt = g_cnt[node]; if (cnt > CAP) cnt = CAP;
            const int* bk = g_bucket + (size_t)node * CAP;
            float acc = (parity == 0) ? hs[node * 16 + ch] : 0.f;
            int j = parity;
            for (; j + 4 <= cnt; j += 4) {
                int r0 = __ldg(bk + j);
                int r1 = __ldg(bk + j + 2);
                acc += hs[r0 * 16 + ch];
                acc += hs[r1 * 16 + ch];
            }
            for (; j < cnt; j += 2) {
                int r = __ldg(bk + j);
                acc += hs[r * 16 + ch];
            }
            acc += __shfl_xor_sync(0xffffffffu, acc, 16);
            float gv = acc * g_dinv[node];

            int o0 = lane, o1 = lane + 32;
            bool has1 = (o1 < OUT_CH);
            float a0 = __ldg(&b2[o0]);
            float a1 = has1 ? __ldg(&b2[o1]) : -INFINITY;
#pragma unroll
            for (int k = 0; k < 16; k++) {
                float gk = __shfl_sync(0xffffffffu, gv, k);
                a0 = fmaf(gk, __ldg(&W2[k * OUT_CH + o0]), a0);
                if (has1) a1 = fmaf(gk, __ldg(&W2[k * OUT_CH + o1]), a1);
            }
            float m = fmaxf(a0, a1);
#pragma unroll
            for (int off = 16; off; off >>= 1)
                m = fmaxf(m, __shfl_xor_sync(0xffffffffu, m, off));
            float s = expf(a0 - m) + (has1 ? expf(a1 - m) : 0.f);
#pragma unroll
            for (int off = 16; off; off >>= 1)
                s += __shfl_xor_sync(0xffffffffu, s, off);
            float lse = m + logf(s);
            out[(size_t)node * OUT_CH + o0] = a0 - lse;
            if (has1) out[(size_t)node * OUT_CH + o1] = a1 - lse;
        }
    }
}

// ---------------------------------------------------------------
extern "C" void kernel_launch(void* const* d_in, const int* in_sizes, int n_in,
                              void* d_out, int out_size) {
    const float* x  = (const float*)d_in[0];
    const void*  ei = d_in[1];
    const float* W1 = (const float*)d_in[2];
    const float* b1 = (const float*)d_in[3];
    const float* W2 = (const float*)d_in[4];
    const float* b2 = (const float*)d_in[5];
    float* out = (float*)d_out;

    static int grid = 0;
    static void* barp = nullptr;
    if (!grid) {
        int sms = 148, bpm = 0;
        cudaDeviceGetAttribute(&sms, cudaDevAttrMultiProcessorCount, 0);
        cudaOccupancyMaxActiveBlocksPerMultiprocessor(&bpm, k_fused, 256, 0);
        if (bpm < 1) bpm = 1;
        grid = sms * bpm;
        cudaGetSymbolAddress(&barp, g_bar);
    }

    // reset grid-barrier state (capture-safe memset node), then one launch
    cudaMemsetAsync(barp, 0, 2 * sizeof(unsigned), 0);
    k_fused<<<grid, 256>>>(x, ei, W1, b1, W2, b2, out);
}

// round 10
// speedup vs baseline: 1.1772x; 1.1772x over previous
#include <cuda_runtime.h>
#include <cuda_fp16.h>
#include <math.h>

#define N_NODES 100000
#define N_EDGES 3200000
#define IN_CH   256
#define HID     16
#define OUT_CH  40
#define CAP     96      // max in-degree capacity (Poisson(32): P(>=96) ~ 1e-18)

// ---- scratch (static device globals; referenced ONLY inside kernels) ----
__device__ int    g_is64;                 // 1 if edge_index is int64, 0 if int32
__device__ int    g_cnt   [N_NODES];      // in-degree
__device__ int    g_bucket[(size_t)N_NODES * CAP];   // source ids per destination
__device__ float  g_dinv  [N_NODES];
__device__ float4 g_t1s   [N_NODES * 4];  // (x @ W1) * dinv[node]  (fp32)
__device__ __half g_hs16  [N_NODES * 16]; // relu(layer1) * dinv    (fp16)

// ---------------------------------------------------------------
// pre: zero counts; thread 0 additionally detects the index dtype
__global__ void k_pre(const int* __restrict__ ei32) {
    int i = blockIdx.x * blockDim.x + threadIdx.x;
    if (i < N_NODES) g_cnt[i] = 0;
    if (i == 0) {
        int is64 = 1;
        for (int j = 0; j < 1024; j++)
            if (ei32[2 * j + 1] != 0) { is64 = 0; break; }
        g_is64 = is64;
    }
}

// bucket build: 4 edges per thread, vectorized index loads
__global__ void k_build(const void* __restrict__ ei) {
    int i4 = blockIdx.x * blockDim.x + threadIdx.x;
    if (i4 * 4 >= N_EDGES) return;
    int r[4], c[4];
    if (!g_is64) {
        const int* e = (const int*)ei;
        int4 rv = __ldg((const int4*)e + i4);
        int4 cv = __ldg((const int4*)(e + N_EDGES) + i4);
        r[0] = rv.x; r[1] = rv.y; r[2] = rv.z; r[3] = rv.w;
        c[0] = cv.x; c[1] = cv.y; c[2] = cv.z; c[3] = cv.w;
    } else {
        const long long* e = (const long long*)ei;
        longlong2 rv0 = __ldg((const longlong2*)e + i4 * 2);
        longlong2 rv1 = __ldg((const longlong2*)e + i4 * 2 + 1);
        longlong2 cv0 = __ldg((const longlong2*)(e + N_EDGES) + i4 * 2);
        longlong2 cv1 = __ldg((const longlong2*)(e + N_EDGES) + i4 * 2 + 1);
        r[0] = (int)rv0.x; r[1] = (int)rv0.y; r[2] = (int)rv1.x; r[3] = (int)rv1.y;
        c[0] = (int)cv0.x; c[1] = (int)cv0.y; c[2] = (int)cv1.x; c[3] = (int)cv1.y;
    }
#pragma unroll
    for (int k = 0; k < 4; k++) {
        int pos = atomicAdd(&g_cnt[c[k]], 1);
        if (pos < CAP) g_bucket[(size_t)c[k] * CAP + pos] = r[k];
    }
}

// ---------------------------------------------------------------
// t1s = (x @ W1) * dinv ; also computes & stores dinv. Register-tiled:
// 1 thread = 1 node, 16 accumulators; x staged via smem transposed
// (xs[k][node], pad 257); W1 broadcast from smem.
__global__ void __launch_bounds__(256) k_gemm1(const float* __restrict__ x,
                                               const float* __restrict__ W1) {
    __shared__ float  xs[32][257];
    __shared__ float4 wsm[256 * 4];
    int t = threadIdx.x;
    int node0 = blockIdx.x * 256;

    const float4* W14 = (const float4*)W1;
#pragma unroll
    for (int j = 0; j < 4; j++) wsm[t + 256 * j] = W14[t + 256 * j];

    float acc[16];
#pragma unroll
    for (int h = 0; h < 16; h++) acc[h] = 0.f;

    int f4 = t & 7;
    int nl = t >> 3;

#pragma unroll 1
    for (int kc = 0; kc < 256; kc += 32) {
        __syncthreads();
#pragma unroll
        for (int rep = 0; rep < 8; rep++) {
            int n = nl + 32 * rep;
            int node = node0 + n;
            float4 v = (node < N_NODES)
                ? __ldg((const float4*)(x + (size_t)node * 256 + kc) + f4)
                : make_float4(0.f, 0.f, 0.f, 0.f);
            xs[f4 * 4 + 0][n] = v.x;
            xs[f4 * 4 + 1][n] = v.y;
            xs[f4 * 4 + 2][n] = v.z;
            xs[f4 * 4 + 3][n] = v.w;
        }
        __syncthreads();
#pragma unroll
        for (int k = 0; k < 32; k++) {
            float xr = xs[k][t];
            float4 w0 = wsm[(kc + k) * 4 + 0];
            float4 w1 = wsm[(kc + k) * 4 + 1];
            float4 w2 = wsm[(kc + k) * 4 + 2];
            float4 w3 = wsm[(kc + k) * 4 + 3];
            acc[0]  = fmaf(xr, w0.x, acc[0]);
            acc[1]  = fmaf(xr, w0.y, acc[1]);
            acc[2]  = fmaf(xr, w0.z, acc[2]);
            acc[3]  = fmaf(xr, w0.w, acc[3]);
            acc[4]  = fmaf(xr, w1.x, acc[4]);
            acc[5]  = fmaf(xr, w1.y, acc[5]);
            acc[6]  = fmaf(xr, w1.z, acc[6]);
            acc[7]  = fmaf(xr, w1.w, acc[7]);
            acc[8]  = fmaf(xr, w2.x, acc[8]);
            acc[9]  = fmaf(xr, w2.y, acc[9]);
            acc[10] = fmaf(xr, w2.z, acc[10]);
            acc[11] = fmaf(xr, w2.w, acc[11]);
            acc[12] = fmaf(xr, w3.x, acc[12]);
            acc[13] = fmaf(xr, w3.y, acc[13]);
            acc[14] = fmaf(xr, w3.z, acc[14]);
            acc[15] = fmaf(xr, w3.w, acc[15]);
        }
    }

    int node = node0 + t;
    if (node < N_NODES) {
        float d = rsqrtf(1.0f + (float)g_cnt[node]);   // fused dinv
        g_dinv[node] = d;
#pragma unroll
        for (int q = 0; q < 4; q++)
            g_t1s[node * 4 + q] = make_float4(acc[q * 4 + 0] * d, acc[q * 4 + 1] * d,
                                              acc[q * 4 + 2] * d, acc[q * 4 + 3] * d);
    }
}

// layer-1 pull-aggregate, 4 lanes per node (lane q owns one float4 quarter).
// writes hs = relu(dinv*(self+sum) + b1) * dinv  as fp16
__global__ void __launch_bounds__(512) k_agg0(const float* __restrict__ b1) {
    int gid = blockIdx.x * blockDim.x + threadIdx.x;
    int node = gid >> 2, q = gid & 3;
    if (node >= N_NODES) return;
    int cnt = g_cnt[node]; if (cnt > CAP) cnt = CAP;
    const int* bk = g_bucket + (size_t)node * CAP;
    const float4* __restrict__ src = g_t1s;
    float4 acc = src[node * 4 + q];   // self-loop term (pre-scaled)
    int j = 0;
    for (; j + 8 <= cnt; j += 8) {
        int4 i0 = *(const int4*)(bk + j);
        int4 i1 = *(const int4*)(bk + j + 4);
        float4 v0 = src[i0.x * 4 + q], v1 = src[i0.y * 4 + q];
        float4 v2 = src[i0.z * 4 + q], v3 = src[i0.w * 4 + q];
        float4 v4 = src[i1.x * 4 + q], v5 = src[i1.y * 4 + q];
        float4 v6 = src[i1.z * 4 + q], v7 = src[i1.w * 4 + q];
        acc.x += ((v0.x + v1.x) + (v2.x + v3.x)) + ((v4.x + v5.x) + (v6.x + v7.x));
        acc.y += ((v0.y + v1.y) + (v2.y + v3.y)) + ((v4.y + v5.y) + (v6.y + v7.y));
        acc.z += ((v0.z + v1.z) + (v2.z + v3.z)) + ((v4.z + v5.z) + (v6.z + v7.z));
        acc.w += ((v0.w + v1.w) + (v2.w + v3.w)) + ((v4.w + v5.w) + (v6.w + v7.w));
    }
    for (; j < cnt; j++) {
        int r = __ldg(bk + j);
        float4 v = src[r * 4 + q];
        acc.x += v.x; acc.y += v.y; acc.z += v.z; acc.w += v.w;
    }
    float d = g_dinv[node];
    float hx = fmaxf(fmaf(acc.x, d, __ldg(&b1[q * 4 + 0])), 0.f) * d;
    float hy = fmaxf(fmaf(acc.y, d, __ldg(&b1[q * 4 + 1])), 0.f) * d;
    float hz = fmaxf(fmaf(acc.z, d, __ldg(&b1[q * 4 + 2])), 0.f) * d;
    float hw = fmaxf(fmaf(acc.w, d, __ldg(&b1[q * 4 + 3])), 0.f) * d;
    __half2 p0 = __floats2half2_rn(hx, hy);
    __half2 p1 = __floats2half2_rn(hz, hw);
    __half2* dst = (__half2*)(g_hs16 + node * 16 + q * 4);
    dst[0] = p0; dst[1] = p1;
}

// fused layer-2 aggregate + GEMM(W2) + log_softmax. One warp per node.
// Lanes 0..15 handle even neighbors, 16..31 odd; combined via shfl_xor(16).
__global__ void __launch_bounds__(256) k_aggfinal(const float* __restrict__ W2,
                                                  const float* __restrict__ b2,
                                                  float* __restrict__ out) {
    int warp = (blockIdx.x * blockDim.x + threadIdx.x) >> 5;
    int lane = threadIdx.x & 31;
    if (warp >= N_NODES) return;
    int node = warp;
    int ch = lane & 15;
    int parity = lane >> 4;

    int cnt = g_cnt[node]; if (cnt > CAP) cnt = CAP;
    const int* bk = g_bucket + (size_t)node * CAP;
    const __half* __restrict__ hs = g_hs16;

    float acc = (parity == 0) ? __half2float(__ldg(&hs[node * 16 + ch])) : 0.f;
    int j = parity;
    for (; j + 4 <= cnt; j += 4) {
        int r0 = __ldg(bk + j);
        int r1 = __ldg(bk + j + 2);
        acc += __half2float(__ldg(&hs[r0 * 16 + ch]));
        acc += __half2float(__ldg(&hs[r1 * 16 + ch]));
    }
    for (; j < cnt; j += 2) {
        int r = __ldg(bk + j);
        acc += __half2float(__ldg(&hs[r * 16 + ch]));
    }
    acc += __shfl_xor_sync(0xffffffffu, acc, 16);
    float gv = acc * g_dinv[node];

    int o0 = lane, o1 = lane + 32;
    bool has1 = (o1 < OUT_CH);
    float acc0 = __ldg(&b2[o0]);
    float acc1 = has1 ? __ldg(&b2[o1]) : -INFINITY;
#pragma unroll
    for (int k = 0; k < 16; k++) {
        float gk = __shfl_sync(0xffffffffu, gv, k);
        acc0 = fmaf(gk, __ldg(&W2[k * OUT_CH + o0]), acc0);
        if (has1) acc1 = fmaf(gk, __ldg(&W2[k * OUT_CH + o1]), acc1);
    }
    float m = fmaxf(acc0, acc1);
#pragma unroll
    for (int off = 16; off; off >>= 1)
        m = fmaxf(m, __shfl_xor_sync(0xffffffffu, m, off));
    float s = expf(acc0 - m) + (has1 ? expf(acc1 - m) : 0.f);
#pragma unroll
    for (int off = 16; off; off >>= 1)
        s += __shfl_xor_sync(0xffffffffu, s, off);
    float lse = m + logf(s);
    out[(size_t)node * OUT_CH + o0] = acc0 - lse;
    if (has1) out[(size_t)node * OUT_CH + o1] = acc1 - lse;
}

// ---------------------------------------------------------------
extern "C" void kernel_launch(void* const* d_in, const int* in_sizes, int n_in,
                              void* d_out, int out_size) {
    const float* x  = (const float*)d_in[0];
    const void*  ei = d_in[1];
    const float* W1 = (const float*)d_in[2];
    const float* b1 = (const float*)d_in[3];
    const float* W2 = (const float*)d_in[4];
    const float* b2 = (const float*)d_in[5];
    float* out = (float*)d_out;

    k_pre   <<<(N_NODES + 255) / 256, 256>>>((const int*)ei);
    k_build <<<(N_EDGES / 4 + 255) / 256, 256>>>(ei);
    k_gemm1 <<<(N_NODES + 255) / 256, 256>>>(x, W1);
    k_agg0  <<<(N_NODES * 4 + 511) / 512, 512>>>(b1);
    k_aggfinal<<<(N_NODES * 32 + 255) / 256, 256>>>(W2, b2, out);
}

// round 11
// speedup vs baseline: 1.2533x; 1.0646x over previous
#include <cuda_runtime.h>
#include <cuda_fp16.h>
#include <math.h>

#define N_NODES 100000
#define N_EDGES 3200000
#define IN_CH   256
#define HID     16
#define OUT_CH  40
#define CAP     96      // max in-degree capacity (Poisson(32): P(>=96) ~ 1e-18)

// ---- scratch (static device globals; referenced ONLY inside kernels) ----
__device__ int    g_is64;
__device__ int    g_cnt   [N_NODES];
__device__ int    g_bucket[(size_t)N_NODES * CAP];
__device__ float  g_dinv  [N_NODES];
__device__ float4 g_t1s   [N_NODES * 4];  // (x @ W1) * dinv[node]  (fp32)
__device__ __half g_hs16  [N_NODES * 16]; // relu(layer1) * dinv    (fp16)

// ---------------------------------------------------------------
__global__ void k_pre(const int* __restrict__ ei32) {
    int i = blockIdx.x * blockDim.x + threadIdx.x;
    if (i < N_NODES) g_cnt[i] = 0;
    if (i == 0) {
        int is64 = 1;
        for (int j = 0; j < 1024; j++)
            if (ei32[2 * j + 1] != 0) { is64 = 0; break; }
        g_is64 = is64;
    }
}

// bucket build: 4 edges per thread, vectorized index loads
__global__ void k_build(const void* __restrict__ ei) {
    int i4 = blockIdx.x * blockDim.x + threadIdx.x;
    if (i4 * 4 >= N_EDGES) return;
    int r[4], c[4];
    if (!g_is64) {
        const int* e = (const int*)ei;
        int4 rv = __ldg((const int4*)e + i4);
        int4 cv = __ldg((const int4*)(e + N_EDGES) + i4);
        r[0] = rv.x; r[1] = rv.y; r[2] = rv.z; r[3] = rv.w;
        c[0] = cv.x; c[1] = cv.y; c[2] = cv.z; c[3] = cv.w;
    } else {
        const long long* e = (const long long*)ei;
        longlong2 rv0 = __ldg((const longlong2*)e + i4 * 2);
        longlong2 rv1 = __ldg((const longlong2*)e + i4 * 2 + 1);
        longlong2 cv0 = __ldg((const longlong2*)(e + N_EDGES) + i4 * 2);
        longlong2 cv1 = __ldg((const longlong2*)(e + N_EDGES) + i4 * 2 + 1);
        r[0] = (int)rv0.x; r[1] = (int)rv0.y; r[2] = (int)rv1.x; r[3] = (int)rv1.y;
        c[0] = (int)cv0.x; c[1] = (int)cv0.y; c[2] = (int)cv1.x; c[3] = (int)cv1.y;
    }
#pragma unroll
    for (int k = 0; k < 4; k++) {
        int pos = atomicAdd(&g_cnt[c[k]], 1);
        if (pos < CAP) g_bucket[(size_t)c[k] * CAP + pos] = r[k];
    }
}

// ---------------------------------------------------------------
// t1s = (x @ W1) * dinv (+stores dinv). Register-tiled, packed f32x2 FMA:
// per k: 1 LDS.32 (x, transposed smem) + 4 LDS.128 (W pairs as double2)
// + 8 fma.rn.f32x2 (16 channel FMAs in 8 instructions, bit-exact fp32).
__global__ void __launch_bounds__(256) k_gemm1(const float* __restrict__ x,
                                               const float* __restrict__ W1) {
    __shared__ float  xs[32][257];
    __shared__ float4 wsm[256 * 4];
    int t = threadIdx.x;
    int node0 = blockIdx.x * 256;

    const float4* W14 = (const float4*)W1;
#pragma unroll
    for (int j = 0; j < 4; j++) wsm[t + 256 * j] = W14[t + 256 * j];

    unsigned long long acc2[8];
#pragma unroll
    for (int h = 0; h < 8; h++) acc2[h] = 0ULL;    // {0.f, 0.f}

    int f4 = t & 7;
    int nl = t >> 3;

#pragma unroll 1
    for (int kc = 0; kc < 256; kc += 32) {
        __syncthreads();
#pragma unroll
        for (int rep = 0; rep < 8; rep++) {
            int n = nl + 32 * rep;
            int node = node0 + n;
            float4 v = (node < N_NODES)
                ? __ldg((const float4*)(x + (size_t)node * 256 + kc) + f4)
                : make_float4(0.f, 0.f, 0.f, 0.f);
            xs[f4 * 4 + 0][n] = v.x;
            xs[f4 * 4 + 1][n] = v.y;
            xs[f4 * 4 + 2][n] = v.z;
            xs[f4 * 4 + 3][n] = v.w;
        }
        __syncthreads();
#pragma unroll
        for (int k = 0; k < 32; k++) {
            float xr = xs[k][t];
            unsigned long long xr2;
            asm("mov.b64 %0, {%1, %1};" : "=l"(xr2) : "f"(xr));
            const double2* wd = (const double2*)(wsm + (kc + k) * 4);
            double2 wa = wd[0], wb = wd[1], wc = wd[2], we = wd[3];
            asm("fma.rn.f32x2 %0, %1, %2, %0;" : "+l"(acc2[0]) : "l"(xr2), "l"(__double_as_longlong(wa.x)));
            asm("fma.rn.f32x2 %0, %1, %2, %0;" : "+l"(acc2[1]) : "l"(xr2), "l"(__double_as_longlong(wa.y)));
            asm("fma.rn.f32x2 %0, %1, %2, %0;" : "+l"(acc2[2]) : "l"(xr2), "l"(__double_as_longlong(wb.x)));
            asm("fma.rn.f32x2 %0, %1, %2, %0;" : "+l"(acc2[3]) : "l"(xr2), "l"(__double_as_longlong(wb.y)));
            asm("fma.rn.f32x2 %0, %1, %2, %0;" : "+l"(acc2[4]) : "l"(xr2), "l"(__double_as_longlong(wc.x)));
            asm("fma.rn.f32x2 %0, %1, %2, %0;" : "+l"(acc2[5]) : "l"(xr2), "l"(__double_as_longlong(wc.y)));
            asm("fma.rn.f32x2 %0, %1, %2, %0;" : "+l"(acc2[6]) : "l"(xr2), "l"(__double_as_longlong(we.x)));
            asm("fma.rn.f32x2 %0, %1, %2, %0;" : "+l"(acc2[7]) : "l"(xr2), "l"(__double_as_longlong(we.y)));
        }
    }

    int node = node0 + t;
    if (node < N_NODES) {
        float d = rsqrtf(1.0f + (float)g_cnt[node]);
        g_dinv[node] = d;
        float acc[16];
#pragma unroll
        for (int j = 0; j < 8; j++) {
            float lo, hi;
            asm("mov.b64 {%0, %1}, %2;" : "=f"(lo), "=f"(hi) : "l"(acc2[j]));
            acc[2 * j] = lo; acc[2 * j + 1] = hi;
        }
#pragma unroll
        for (int q = 0; q < 4; q++)
            g_t1s[node * 4 + q] = make_float4(acc[q * 4 + 0] * d, acc[q * 4 + 1] * d,
                                              acc[q * 4 + 2] * d, acc[q * 4 + 3] * d);
    }
}

// layer-1 pull-aggregate, 4 lanes per node; writes fp16 hs
__global__ void __launch_bounds__(512) k_agg0(const float* __restrict__ b1) {
    int gid = blockIdx.x * blockDim.x + threadIdx.x;
    int node = gid >> 2, q = gid & 3;
    if (node >= N_NODES) return;
    int cnt = g_cnt[node]; if (cnt > CAP) cnt = CAP;
    const int* bk = g_bucket + (size_t)node * CAP;
    const float4* __restrict__ src = g_t1s;
    float4 acc = src[node * 4 + q];
    int j = 0;
    for (; j + 8 <= cnt; j += 8) {
        int4 i0 = *(const int4*)(bk + j);
        int4 i1 = *(const int4*)(bk + j + 4);
        float4 v0 = src[i0.x * 4 + q], v1 = src[i0.y * 4 + q];
        float4 v2 = src[i0.z * 4 + q], v3 = src[i0.w * 4 + q];
        float4 v4 = src[i1.x * 4 + q], v5 = src[i1.y * 4 + q];
        float4 v6 = src[i1.z * 4 + q], v7 = src[i1.w * 4 + q];
        acc.x += ((v0.x + v1.x) + (v2.x + v3.x)) + ((v4.x + v5.x) + (v6.x + v7.x));
        acc.y += ((v0.y + v1.y) + (v2.y + v3.y)) + ((v4.y + v5.y) + (v6.y + v7.y));
        acc.z += ((v0.z + v1.z) + (v2.z + v3.z)) + ((v4.z + v5.z) + (v6.z + v7.z));
        acc.w += ((v0.w + v1.w) + (v2.w + v3.w)) + ((v4.w + v5.w) + (v6.w + v7.w));
    }
    for (; j < cnt; j++) {
        int r = __ldg(bk + j);
        float4 v = src[r * 4 + q];
        acc.x += v.x; acc.y += v.y; acc.z += v.z; acc.w += v.w;
    }
    float d = g_dinv[node];
    float hx = fmaxf(fmaf(acc.x, d, __ldg(&b1[q * 4 + 0])), 0.f) * d;
    float hy = fmaxf(fmaf(acc.y, d, __ldg(&b1[q * 4 + 1])), 0.f) * d;
    float hz = fmaxf(fmaf(acc.z, d, __ldg(&b1[q * 4 + 2])), 0.f) * d;
    float hw = fmaxf(fmaf(acc.w, d, __ldg(&b1[q * 4 + 3])), 0.f) * d;
    __half2* dst = (__half2*)(g_hs16 + node * 16 + q * 4);
    dst[0] = __floats2half2_rn(hx, hy);
    dst[1] = __floats2half2_rn(hz, hw);
}

// fused layer-2 aggregate + GEMM(W2) + log_softmax. One warp per node.
// slot-parallel: lane = slot(0..3)*8 + c2(0..7); each iteration covers
// 4 neighbors (1 coalesced idx load + 1 half2 gather per lane).
__global__ void __launch_bounds__(256) k_aggfinal(const float* __restrict__ W2,
                                                  const float* __restrict__ b2,
                                                  float* __restrict__ out) {
    int warp = (blockIdx.x * blockDim.x + threadIdx.x) >> 5;
    int lane = threadIdx.x & 31;
    if (warp >= N_NODES) return;
    int node = warp;
    int slot = lane >> 3;     // 0..3 : neighbor slot
    int c2   = lane & 7;      // channel pair 0..7

    int cnt = g_cnt[node]; if (cnt > CAP) cnt = CAP;
    const int* bk = g_bucket + (size_t)node * CAP;
    const __half2* __restrict__ hs2 = (const __half2*)g_hs16;

    float2 acc = make_float2(0.f, 0.f);
    if (slot == 0) {                         // self-loop term
        float2 v = __half22float2(__ldg(&hs2[node * 8 + c2]));
        acc.x = v.x; acc.y = v.y;
    }
    int j = slot;
    for (; j + 4 < cnt; j += 8) {            // two independent chains
        int r0 = __ldg(bk + j);
        int r1 = __ldg(bk + j + 4);
        float2 v0 = __half22float2(__ldg(&hs2[r0 * 8 + c2]));
        float2 v1 = __half22float2(__ldg(&hs2[r1 * 8 + c2]));
        acc.x += v0.x + v1.x;
        acc.y += v0.y + v1.y;
    }
    if (j < cnt) {
        int r = __ldg(bk + j);
        float2 v = __half22float2(__ldg(&hs2[r * 8 + c2]));
        acc.x += v.x; acc.y += v.y;
    }
    // reduce across the 4 slots
    acc.x += __shfl_xor_sync(0xffffffffu, acc.x, 8);
    acc.y += __shfl_xor_sync(0xffffffffu, acc.y, 8);
    acc.x += __shfl_xor_sync(0xffffffffu, acc.x, 16);
    acc.y += __shfl_xor_sync(0xffffffffu, acc.y, 16);
    // redistribute: lane wants channel ch = lane & 15, held on lane ch>>1
    int ch = lane & 15;
    float vx = __shfl_sync(0xffffffffu, acc.x, ch >> 1);
    float vy = __shfl_sync(0xffffffffu, acc.y, ch >> 1);
    float gv = ((ch & 1) ? vy : vx) * g_dinv[node];

    int o0 = lane, o1 = lane + 32;
    bool has1 = (o1 < OUT_CH);
    float acc0 = __ldg(&b2[o0]);
    float acc1 = has1 ? __ldg(&b2[o1]) : -INFINITY;
#pragma unroll
    for (int k = 0; k < 16; k++) {
        float gk = __shfl_sync(0xffffffffu, gv, k);
        acc0 = fmaf(gk, __ldg(&W2[k * OUT_CH + o0]), acc0);
        if (has1) acc1 = fmaf(gk, __ldg(&W2[k * OUT_CH + o1]), acc1);
    }
    float m = fmaxf(acc0, acc1);
#pragma unroll
    for (int off = 16; off; off >>= 1)
        m = fmaxf(m, __shfl_xor_sync(0xffffffffu, m, off));
    float s = expf(acc0 - m) + (has1 ? expf(acc1 - m) : 0.f);
#pragma unroll
    for (int off = 16; off; off >>= 1)
        s += __shfl_xor_sync(0xffffffffu, s, off);
    float lse = m + logf(s);
    out[(size_t)node * OUT_CH + o0] = acc0 - lse;
    if (has1) out[(size_t)node * OUT_CH + o1] = acc1 - lse;
}

// ---------------------------------------------------------------
extern "C" void kernel_launch(void* const* d_in, const int* in_sizes, int n_in,
                              void* d_out, int out_size) {
    const float* x  = (const float*)d_in[0];
    const void*  ei = d_in[1];
    const float* W1 = (const float*)d_in[2];
    const float* b1 = (const float*)d_in[3];
    const float* W2 = (const float*)d_in[4];
    const float* b2 = (const float*)d_in[5];
    float* out = (float*)d_out;

    k_pre   <<<(N_NODES + 255) / 256, 256>>>((const int*)ei);
    k_build <<<(N_EDGES / 4 + 255) / 256, 256>>>(ei);
    k_gemm1 <<<(N_NODES + 255) / 256, 256>>>(x, W1);
    k_agg0  <<<(N_NODES * 4 + 511) / 512, 512>>>(b1);
    k_aggfinal<<<(N_NODES * 32 + 255) / 256, 256>>>(W2, b2, out);
}

// round 12
// speedup vs baseline: 1.2697x; 1.0131x over previous
#include <cuda_runtime.h>
#include <cuda_fp16.h>
#include <math.h>

#define N_NODES 100000
#define N_EDGES 3200000
#define IN_CH   256
#define HID     16
#define OUT_CH  40
#define CAP     96      // max in-degree capacity (Poisson(32): P(>=96) ~ 1e-18)

// ---- scratch (static device globals; referenced ONLY inside kernels) ----
__device__ int    g_cnt   [N_NODES];
__device__ int    g_bucket[(size_t)N_NODES * CAP];
__device__ float  g_dinv  [N_NODES];
__device__ __align__(16) __half g_t1s16[N_NODES * 16]; // (x@W1)*dinv, fp16
__device__ __align__(16) __half g_hs16 [N_NODES * 16]; // relu(l1)*dinv, fp16

// ---------------------------------------------------------------
// bucket build with inline dtype detect: each thread checks 8 odd 32-bit
// words of the head of ei; for int32 ids in [0,1e5) P(all zero) ~ 1e-40.
__global__ void k_build(const void* __restrict__ ei) {
    const int* e32 = (const int*)ei;
    int z = 0;
#pragma unroll
    for (int j = 0; j < 8; j++) z |= __ldg(&e32[2 * j + 1]);
    bool is64 = (z == 0);

    int i4 = blockIdx.x * blockDim.x + threadIdx.x;
    if (i4 * 4 >= N_EDGES) return;
    int r[4], c[4];
    if (!is64) {
        const int* e = (const int*)ei;
        int4 rv = __ldg((const int4*)e + i4);
        int4 cv = __ldg((const int4*)(e + N_EDGES) + i4);
        r[0] = rv.x; r[1] = rv.y; r[2] = rv.z; r[3] = rv.w;
        c[0] = cv.x; c[1] = cv.y; c[2] = cv.z; c[3] = cv.w;
    } else {
        const long long* e = (const long long*)ei;
        longlong2 a0 = __ldg((const longlong2*)e + i4 * 2);
        longlong2 a1 = __ldg((const longlong2*)e + i4 * 2 + 1);
        longlong2 b0 = __ldg((const longlong2*)(e + N_EDGES) + i4 * 2);
        longlong2 b1 = __ldg((const longlong2*)(e + N_EDGES) + i4 * 2 + 1);
        r[0] = (int)a0.x; r[1] = (int)a0.y; r[2] = (int)a1.x; r[3] = (int)a1.y;
        c[0] = (int)b0.x; c[1] = (int)b0.y; c[2] = (int)b1.x; c[3] = (int)b1.y;
    }
#pragma unroll
    for (int k = 0; k < 4; k++) {
        int pos = atomicAdd(&g_cnt[c[k]], 1);
        if (pos < CAP) g_bucket[(size_t)c[k] * CAP + pos] = r[k];
    }
}

// ---------------------------------------------------------------
// t1s16 = fp16((x @ W1) * dinv); stores dinv. Register-tiled, f32x2 FMA.
__global__ void __launch_bounds__(256) k_gemm1(const float* __restrict__ x,
                                               const float* __restrict__ W1) {
    __shared__ float  xs[32][257];
    __shared__ float4 wsm[256 * 4];
    int t = threadIdx.x;
    int node0 = blockIdx.x * 256;

    const float4* W14 = (const float4*)W1;
#pragma unroll
    for (int j = 0; j < 4; j++) wsm[t + 256 * j] = W14[t + 256 * j];

    unsigned long long acc2[8];
#pragma unroll
    for (int h = 0; h < 8; h++) acc2[h] = 0ULL;

    int f4 = t & 7;
    int nl = t >> 3;

#pragma unroll 1
    for (int kc = 0; kc < 256; kc += 32) {
        __syncthreads();
#pragma unroll
        for (int rep = 0; rep < 8; rep++) {
            int n = nl + 32 * rep;
            int node = node0 + n;
            float4 v = (node < N_NODES)
                ? __ldg((const float4*)(x + (size_t)node * 256 + kc) + f4)
                : make_float4(0.f, 0.f, 0.f, 0.f);
            xs[f4 * 4 + 0][n] = v.x;
            xs[f4 * 4 + 1][n] = v.y;
            xs[f4 * 4 + 2][n] = v.z;
            xs[f4 * 4 + 3][n] = v.w;
        }
        __syncthreads();
#pragma unroll
        for (int k = 0; k < 32; k++) {
            float xr = xs[k][t];
            unsigned long long xr2;
            asm("mov.b64 %0, {%1, %1};" : "=l"(xr2) : "f"(xr));
            const double2* wd = (const double2*)(wsm + (kc + k) * 4);
            double2 wa = wd[0], wb = wd[1], wc = wd[2], we = wd[3];
            asm("fma.rn.f32x2 %0, %1, %2, %0;" : "+l"(acc2[0]) : "l"(xr2), "l"(__double_as_longlong(wa.x)));
            asm("fma.rn.f32x2 %0, %1, %2, %0;" : "+l"(acc2[1]) : "l"(xr2), "l"(__double_as_longlong(wa.y)));
            asm("fma.rn.f32x2 %0, %1, %2, %0;" : "+l"(acc2[2]) : "l"(xr2), "l"(__double_as_longlong(wb.x)));
            asm("fma.rn.f32x2 %0, %1, %2, %0;" : "+l"(acc2[3]) : "l"(xr2), "l"(__double_as_longlong(wb.y)));
            asm("fma.rn.f32x2 %0, %1, %2, %0;" : "+l"(acc2[4]) : "l"(xr2), "l"(__double_as_longlong(wc.x)));
            asm("fma.rn.f32x2 %0, %1, %2, %0;" : "+l"(acc2[5]) : "l"(xr2), "l"(__double_as_longlong(wc.y)));
            asm("fma.rn.f32x2 %0, %1, %2, %0;" : "+l"(acc2[6]) : "l"(xr2), "l"(__double_as_longlong(we.x)));
            asm("fma.rn.f32x2 %0, %1, %2, %0;" : "+l"(acc2[7]) : "l"(xr2), "l"(__double_as_longlong(we.y)));
        }
    }

    int node = node0 + t;
    if (node < N_NODES) {
        float d = rsqrtf(1.0f + (float)g_cnt[node]);
        g_dinv[node] = d;
        __half2 h2[8];
#pragma unroll
        for (int j = 0; j < 8; j++) {
            float lo, hi;
            asm("mov.b64 {%0, %1}, %2;" : "=f"(lo), "=f"(hi) : "l"(acc2[j]));
            h2[j] = __floats2half2_rn(lo * d, hi * d);
        }
        uint4* dst = (uint4*)(g_t1s16 + (size_t)node * 16);
        dst[0] = *(uint4*)&h2[0];
        dst[1] = *(uint4*)&h2[4];
    }
}

// layer-1 pull-aggregate: 8 lanes/node (slot 0..3 x half 0..1); each lane
// gathers uint4 = 8 fp16 channels per neighbor; fp32 accumulate; writes hs fp16.
__global__ void __launch_bounds__(512) k_agg0(const float* __restrict__ b1) {
    int gid = blockIdx.x * blockDim.x + threadIdx.x;
    int node = gid >> 3;
    if (node >= N_NODES) return;
    int sub  = gid & 7;
    int slot = sub >> 1;
    int half = sub & 1;

    int cnt = g_cnt[node]; if (cnt > CAP) cnt = CAP;
    const int* bk = g_bucket + (size_t)node * CAP;
    const uint4* __restrict__ src = (const uint4*)g_t1s16;   // 2 per node

    float acc[8];
#pragma unroll
    for (int i = 0; i < 8; i++) acc[i] = 0.f;

#define ADDV(u) do { \
        __half2* _p = (__half2*)&(u); \
        float2 _f0 = __half22float2(_p[0]); \
        float2 _f1 = __half22float2(_p[1]); \
        float2 _f2 = __half22float2(_p[2]); \
        float2 _f3 = __half22float2(_p[3]); \
        acc[0] += _f0.x; acc[1] += _f0.y; acc[2] += _f1.x; acc[3] += _f1.y; \
        acc[4] += _f2.x; acc[5] += _f2.y; acc[6] += _f3.x; acc[7] += _f3.y; \
    } while (0)

    if (slot == 0) { uint4 v = src[node * 2 + half]; ADDV(v); }   // self term
    int j = slot;
    for (; j + 4 < cnt; j += 8) {                 // two independent chains
        int r0 = __ldg(bk + j);
        int r1 = __ldg(bk + j + 4);
        uint4 v0 = __ldg(&src[r0 * 2 + half]);
        uint4 v1 = __ldg(&src[r1 * 2 + half]);
        ADDV(v0); ADDV(v1);
    }
    if (j < cnt) {
        int r = __ldg(bk + j);
        uint4 v = __ldg(&src[r * 2 + half]);
        ADDV(v);
    }
#undef ADDV

    // reduce over the 4 slots (lane bits 1..2 within the 8-lane group)
#pragma unroll
    for (int i = 0; i < 8; i++) {
        acc[i] += __shfl_xor_sync(0xffffffffu, acc[i], 2);
        acc[i] += __shfl_xor_sync(0xffffffffu, acc[i], 4);
    }

    if (slot == 0) {
        float d = g_dinv[node];
        __half2 h2[4];
#pragma unroll
        for (int p = 0; p < 4; p++) {
            float a = fmaxf(fmaf(acc[2 * p + 0], d, __ldg(&b1[half * 8 + 2 * p + 0])), 0.f) * d;
            float b = fmaxf(fmaf(acc[2 * p + 1], d, __ldg(&b1[half * 8 + 2 * p + 1])), 0.f) * d;
            h2[p] = __floats2half2_rn(a, b);
        }
        ((uint4*)(g_hs16 + (size_t)node * 16))[half] = *(uint4*)&h2[0];
    }
}

// fused layer-2 aggregate + GEMM(W2) + log_softmax. One warp per node.
// slot-parallel: lane = slot(0..3)*8 + c2(0..7).
__global__ void __launch_bounds__(256) k_aggfinal(const float* __restrict__ W2,
                                                  const float* __restrict__ b2,
                                                  float* __restrict__ out) {
    int warp = (blockIdx.x * blockDim.x + threadIdx.x) >> 5;
    int lane = threadIdx.x & 31;
    if (warp >= N_NODES) return;
    int node = warp;
    int slot = lane >> 3;
    int c2   = lane & 7;

    int cnt = g_cnt[node]; if (cnt > CAP) cnt = CAP;
    const int* bk = g_bucket + (size_t)node * CAP;
    const __half2* __restrict__ hs2 = (const __half2*)g_hs16;

    float2 acc = make_float2(0.f, 0.f);
    if (slot == 0) {
        float2 v = __half22float2(__ldg(&hs2[node * 8 + c2]));
        acc.x = v.x; acc.y = v.y;
    }
    int j = slot;
    for (; j + 4 < cnt; j += 8) {
        int r0 = __ldg(bk + j);
        int r1 = __ldg(bk + j + 4);
        float2 v0 = __half22float2(__ldg(&hs2[r0 * 8 + c2]));
        float2 v1 = __half22float2(__ldg(&hs2[r1 * 8 + c2]));
        acc.x += v0.x + v1.x;
        acc.y += v0.y + v1.y;
    }
    if (j < cnt) {
        int r = __ldg(bk + j);
        float2 v = __half22float2(__ldg(&hs2[r * 8 + c2]));
        acc.x += v.x; acc.y += v.y;
    }
    acc.x += __shfl_xor_sync(0xffffffffu, acc.x, 8);
    acc.y += __shfl_xor_sync(0xffffffffu, acc.y, 8);
    acc.x += __shfl_xor_sync(0xffffffffu, acc.x, 16);
    acc.y += __shfl_xor_sync(0xffffffffu, acc.y, 16);
    int ch = lane & 15;
    float vx = __shfl_sync(0xffffffffu, acc.x, ch >> 1);
    float vy = __shfl_sync(0xffffffffu, acc.y, ch >> 1);
    float gv = ((ch & 1) ? vy : vx) * g_dinv[node];

    int o0 = lane, o1 = lane + 32;
    bool has1 = (o1 < OUT_CH);
    float acc0 = __ldg(&b2[o0]);
    float acc1 = has1 ? __ldg(&b2[o1]) : -INFINITY;
#pragma unroll
    for (int k = 0; k < 16; k++) {
        float gk = __shfl_sync(0xffffffffu, gv, k);
        acc0 = fmaf(gk, __ldg(&W2[k * OUT_CH + o0]), acc0);
        if (has1) acc1 = fmaf(gk, __ldg(&W2[k * OUT_CH + o1]), acc1);
    }
    float m = fmaxf(acc0, acc1);
#pragma unroll
    for (int off = 16; off; off >>= 1)
        m = fmaxf(m, __shfl_xor_sync(0xffffffffu, m, off));
    float s = expf(acc0 - m) + (has1 ? expf(acc1 - m) : 0.f);
#pragma unroll
    for (int off = 16; off; off >>= 1)
        s += __shfl_xor_sync(0xffffffffu, s, off);
    float lse = m + logf(s);
    out[(size_t)node * OUT_CH + o0] = acc0 - lse;
    if (has1) out[(size_t)node * OUT_CH + o1] = acc1 - lse;
}

// ---------------------------------------------------------------
extern "C" void kernel_launch(void* const* d_in, const int* in_sizes, int n_in,
                              void* d_out, int out_size) {
    const float* x  = (const float*)d_in[0];
    const void*  ei = d_in[1];
    const float* W1 = (const float*)d_in[2];
    const float* b1 = (const float*)d_in[3];
    const float* W2 = (const float*)d_in[4];
    const float* b2 = (const float*)d_in[5];
    float* out = (float*)d_out;

    static void* cntp = nullptr;
    if (!cntp) cudaGetSymbolAddress(&cntp, g_cnt);

    cudaMemsetAsync(cntp, 0, N_NODES * sizeof(int), 0);
    k_build <<<(N_EDGES / 4 + 255) / 256, 256>>>(ei);
    k_gemm1 <<<(N_NODES + 255) / 256, 256>>>(x, W1);
    k_agg0  <<<(N_NODES * 8 + 511) / 512, 512>>>(b1);
    k_aggfinal<<<(N_NODES * 32 + 255) / 256, 256>>>(W2, b2, out);
}